// round 8
// baseline (speedup 1.0000x reference)
#include <cuda_runtime.h>
#include <cuda_bf16.h>
#include <cstdint>

#define N_EDGES 800000
#define N_NODES 50000
#define MID 3
#define NVEC 32

// Per-node accumulators: [N_NODES, MID, NVEC] floats, viewed as float4.
// 50000 * 96 floats = 4.8M floats = 1.2M float4 each (18.3 MB each; both fit in L2).
__device__ float4 g_xn1[N_NODES * MID * NVEC / 4];
__device__ float4 g_xn2[N_NODES * MID * NVEC / 4];

__device__ __forceinline__ void red_add_v4(float4* addr, float4 v) {
    asm volatile("red.global.add.v4.f32 [%0], {%1, %2, %3, %4};"
                 :: "l"(addr), "f"(v.x), "f"(v.y), "f"(v.z), "f"(v.w)
                 : "memory");
}

// ---------------------------------------------------------------------------
// Kernel 1: zero the accumulators (graph-capturable; no memset API needed)
// ---------------------------------------------------------------------------
__global__ void zero_accum_kernel() {
    int i = blockIdx.x * blockDim.x + threadIdx.x;
    const float4 z = make_float4(0.f, 0.f, 0.f, 0.f);
    if (i < N_NODES * MID * NVEC / 4) {
        g_xn1[i] = z;
        g_xn2[i] = z;
    }
}

// ---------------------------------------------------------------------------
// Kernel 2: edge scatter.  8 threads per edge; each thread owns 4 of the 32
// vector lanes (float4).  W read once per edge, reused across MID=3.
// wxe = W * xe scattered with red.v4 into xn1[dst] and xn2[src].
// ---------------------------------------------------------------------------
__global__ void edge_scatter_kernel(const float4* __restrict__ xe4,   // [E*3*8]
                                    const float4* __restrict__ W4,    // [E*8]
                                    const int*    __restrict__ src,
                                    const int*    __restrict__ dst) {
    int gid = blockIdx.x * blockDim.x + threadIdx.x;
    int e   = gid >> 3;
    int sub = gid & 7;
    if (e >= N_EDGES) return;

    float4 w = __ldg(&W4[e * 8 + sub]);
    int d = __ldg(&dst[e]);
    int s = __ldg(&src[e]);

    float4* p1 = &g_xn1[d * (MID * 8) + sub];
    float4* p2 = &g_xn2[s * (MID * 8) + sub];

#pragma unroll
    for (int m = 0; m < MID; m++) {
        float4 x = __ldg(&xe4[(e * MID + m) * 8 + sub]);
        float4 v;
        v.x = w.x * x.x;
        v.y = w.y * x.y;
        v.z = w.z * x.z;
        v.w = w.w * x.w;
        red_add_v4(p1 + m * 8, v);
        red_add_v4(p2 + m * 8, v);
    }
}

// ---------------------------------------------------------------------------
// Kernel 3: per-node epilogue.
//   out = xn1 @ Ma + xn2 @ Mb, Ma = 0.5*(M1+M2), Mb = 0.5*(M2-M1)
// One warp per node.  Lane v holds xn rows; results built by shuffle
// broadcast against Ma/Mb staged in shared memory.
// ---------------------------------------------------------------------------
__global__ void node_mix_kernel(const float* __restrict__ M1,
                                const float* __restrict__ M2,
                                float* __restrict__ out) {
    __shared__ float sMa[NVEC * NVEC];
    __shared__ float sMb[NVEC * NVEC];

    for (int i = threadIdx.x; i < NVEC * NVEC; i += blockDim.x) {
        float m1 = M1[i], m2 = M2[i];
        sMa[i] = 0.5f * (m1 + m2);
        sMb[i] = 0.5f * (m2 - m1);
    }
    __syncthreads();

    int gwarp = (blockIdx.x * blockDim.x + threadIdx.x) >> 5;
    int lane  = threadIdx.x & 31;
    if (gwarp >= N_NODES) return;

    const float* x1 = reinterpret_cast<const float*>(g_xn1) + gwarp * (MID * NVEC);
    const float* x2 = reinterpret_cast<const float*>(g_xn2) + gwarp * (MID * NVEC);

    float a1_0 = x1[lane],          a2_0 = x2[lane];
    float a1_1 = x1[NVEC + lane],   a2_1 = x2[NVEC + lane];
    float a1_2 = x1[2*NVEC + lane], a2_2 = x2[2*NVEC + lane];

    float o0 = 0.f, o1 = 0.f, o2 = 0.f;
#pragma unroll
    for (int v = 0; v < NVEC; v++) {
        float b1 = sMa[v * NVEC + lane];
        float b2 = sMb[v * NVEC + lane];
        o0 = fmaf(__shfl_sync(0xffffffffu, a1_0, v), b1,
             fmaf(__shfl_sync(0xffffffffu, a2_0, v), b2, o0));
        o1 = fmaf(__shfl_sync(0xffffffffu, a1_1, v), b1,
             fmaf(__shfl_sync(0xffffffffu, a2_1, v), b2, o1));
        o2 = fmaf(__shfl_sync(0xffffffffu, a1_2, v), b1,
             fmaf(__shfl_sync(0xffffffffu, a2_2, v), b2, o2));
    }

    float* o = out + gwarp * (MID * NVEC);
    o[lane]          = o0;
    o[NVEC + lane]   = o1;
    o[2*NVEC + lane] = o2;
}

// ---------------------------------------------------------------------------
// Launch.  Inputs (metadata order): xe, W, M1, M2, xe_src, xe_dst, n_nodes
// ---------------------------------------------------------------------------
extern "C" void kernel_launch(void* const* d_in, const int* in_sizes, int n_in,
                              void* d_out, int out_size) {
    const float4* xe4 = (const float4*)d_in[0];
    const float4* W4  = (const float4*)d_in[1];
    const float*  M1  = (const float*)d_in[2];
    const float*  M2  = (const float*)d_in[3];
    const int*    src = (const int*)d_in[4];
    const int*    dst = (const int*)d_in[5];
    float* out = (float*)d_out;

    // 1) zero accumulators
    {
        int n = N_NODES * MID * NVEC / 4;
        zero_accum_kernel<<<(n + 255) / 256, 256>>>();
    }
    // 2) edge scatter (8 threads per edge)
    {
        long long nthreads = (long long)N_EDGES * 8;
        int blocks = (int)((nthreads + 255) / 256);
        edge_scatter_kernel<<<blocks, 256>>>(xe4, W4, src, dst);
    }
    // 3) per-node mix (one warp per node)
    {
        long long nthreads = (long long)N_NODES * 32;
        int blocks = (int)((nthreads + 255) / 256);
        node_mix_kernel<<<blocks, 256>>>(M1, M2, out);
    }
}

// round 9
// speedup vs baseline: 1.1767x; 1.1767x over previous
#include <cuda_runtime.h>
#include <cuda_fp16.h>
#include <cuda_bf16.h>
#include <cstdint>

#define N_EDGES 800000
#define N_NODES 50000
#define MID 3
#define NVEC 32

// Per-node fp16 accumulators: [N_NODES, MID*NVEC] halves = 192 B per node row.
// Each array is 9.6 MB; both fit comfortably in L2 (126 MB) so the atomic RMW
// traffic never leaves L2.
__device__ __half g_xn1[N_NODES * MID * NVEC];
__device__ __half g_xn2[N_NODES * MID * NVEC];

__device__ __forceinline__ unsigned pack_h2(float a, float b) {
    __half2 h = __floats2half2_rn(a, b);
    return *reinterpret_cast<unsigned*>(&h);
}

// 16-byte packed fp16 reduction: adds 8 half values in one RED op.
__device__ __forceinline__ void red_add_v4_f16x2(void* addr,
                                                 unsigned h0, unsigned h1,
                                                 unsigned h2, unsigned h3) {
    asm volatile("red.global.add.noftz.v4.f16x2 [%0], {%1, %2, %3, %4};"
                 :: "l"(addr), "r"(h0), "r"(h1), "r"(h2), "r"(h3)
                 : "memory");
}

// ---------------------------------------------------------------------------
// Kernel 1: zero the accumulators (both arrays, 19.2 MB total, uint4 stores)
// ---------------------------------------------------------------------------
__global__ void zero_accum_kernel() {
    int i = blockIdx.x * blockDim.x + threadIdx.x;
    const uint4 z = make_uint4(0u, 0u, 0u, 0u);
    const int n = N_NODES * MID * NVEC * 2 / 16;  // uint4 count per array
    if (i < n) {
        reinterpret_cast<uint4*>(g_xn1)[i] = z;
        reinterpret_cast<uint4*>(g_xn2)[i] = z;
    }
}

// ---------------------------------------------------------------------------
// Kernel 2: edge scatter.  4 threads per edge; each thread owns 8 of the 32
// vector lanes.  Per thread: 2 LDG.128 for W, 2 LDG.128 per mid for xe,
// 1 RED.v4.f16x2 per (mid, target) -> 6 REDs total (vs 12 in fp32 version).
// ---------------------------------------------------------------------------
__global__ void __launch_bounds__(256)
edge_scatter_kernel(const float4* __restrict__ xe4,   // [E*3*8]
                    const float4* __restrict__ W4,    // [E*8]
                    const int*    __restrict__ src,
                    const int*    __restrict__ dst) {
    int gid = blockIdx.x * blockDim.x + threadIdx.x;
    int e   = gid >> 2;
    int sub = gid & 3;        // owns halves [sub*8, sub*8+8) of each 32-vec
    if (e >= N_EDGES) return;

    // W lanes sub*8 .. sub*8+7  (two float4)
    const float4* Wp = W4 + e * 8 + sub * 2;
    float4 w0 = __ldg(&Wp[0]);
    float4 w1 = __ldg(&Wp[1]);

    int d = __ldg(&dst[e]);
    int s = __ldg(&src[e]);

    // byte offsets into half accumulators: node*192 + m*64 + sub*16
    char* p1 = reinterpret_cast<char*>(g_xn1) + (size_t)d * (MID * NVEC * 2) + sub * 16;
    char* p2 = reinterpret_cast<char*>(g_xn2) + (size_t)s * (MID * NVEC * 2) + sub * 16;

#pragma unroll
    for (int m = 0; m < MID; m++) {
        const float4* xp = xe4 + (e * MID + m) * 8 + sub * 2;
        float4 x0 = __ldg(&xp[0]);
        float4 x1 = __ldg(&xp[1]);

        unsigned h0 = pack_h2(w0.x * x0.x, w0.y * x0.y);
        unsigned h1 = pack_h2(w0.z * x0.z, w0.w * x0.w);
        unsigned h2 = pack_h2(w1.x * x1.x, w1.y * x1.y);
        unsigned h3 = pack_h2(w1.z * x1.z, w1.w * x1.w);

        red_add_v4_f16x2(p1 + m * (NVEC * 2), h0, h1, h2, h3);
        red_add_v4_f16x2(p2 + m * (NVEC * 2), h0, h1, h2, h3);
    }
}

// ---------------------------------------------------------------------------
// Kernel 3: per-node epilogue (fp32 math).
//   out = xn1 @ Ma + xn2 @ Mb, Ma = 0.5*(M1+M2), Mb = 0.5*(M2-M1)
// One warp per node; shuffle-broadcast GEMV against Ma/Mb in shared memory.
// ---------------------------------------------------------------------------
__global__ void node_mix_kernel(const float* __restrict__ M1,
                                const float* __restrict__ M2,
                                float* __restrict__ out) {
    __shared__ float sMa[NVEC * NVEC];
    __shared__ float sMb[NVEC * NVEC];

    for (int i = threadIdx.x; i < NVEC * NVEC; i += blockDim.x) {
        float m1 = M1[i], m2 = M2[i];
        sMa[i] = 0.5f * (m1 + m2);
        sMb[i] = 0.5f * (m2 - m1);
    }
    __syncthreads();

    int gwarp = (blockIdx.x * blockDim.x + threadIdx.x) >> 5;
    int lane  = threadIdx.x & 31;
    if (gwarp >= N_NODES) return;

    const __half* x1 = g_xn1 + (size_t)gwarp * (MID * NVEC);
    const __half* x2 = g_xn2 + (size_t)gwarp * (MID * NVEC);

    float a1_0 = __half2float(x1[lane]);
    float a2_0 = __half2float(x2[lane]);
    float a1_1 = __half2float(x1[NVEC + lane]);
    float a2_1 = __half2float(x2[NVEC + lane]);
    float a1_2 = __half2float(x1[2 * NVEC + lane]);
    float a2_2 = __half2float(x2[2 * NVEC + lane]);

    float o0 = 0.f, o1 = 0.f, o2 = 0.f;
#pragma unroll
    for (int v = 0; v < NVEC; v++) {
        float b1 = sMa[v * NVEC + lane];
        float b2 = sMb[v * NVEC + lane];
        o0 = fmaf(__shfl_sync(0xffffffffu, a1_0, v), b1,
             fmaf(__shfl_sync(0xffffffffu, a2_0, v), b2, o0));
        o1 = fmaf(__shfl_sync(0xffffffffu, a1_1, v), b1,
             fmaf(__shfl_sync(0xffffffffu, a2_1, v), b2, o1));
        o2 = fmaf(__shfl_sync(0xffffffffu, a1_2, v), b1,
             fmaf(__shfl_sync(0xffffffffu, a2_2, v), b2, o2));
    }

    float* o = out + (size_t)gwarp * (MID * NVEC);
    o[lane]            = o0;
    o[NVEC + lane]     = o1;
    o[2 * NVEC + lane] = o2;
}

// ---------------------------------------------------------------------------
// Launch.  Inputs (metadata order): xe, W, M1, M2, xe_src, xe_dst, n_nodes
// ---------------------------------------------------------------------------
extern "C" void kernel_launch(void* const* d_in, const int* in_sizes, int n_in,
                              void* d_out, int out_size) {
    const float4* xe4 = (const float4*)d_in[0];
    const float4* W4  = (const float4*)d_in[1];
    const float*  M1  = (const float*)d_in[2];
    const float*  M2  = (const float*)d_in[3];
    const int*    src = (const int*)d_in[4];
    const int*    dst = (const int*)d_in[5];
    float* out = (float*)d_out;

    // 1) zero accumulators
    {
        int n = N_NODES * MID * NVEC * 2 / 16;
        zero_accum_kernel<<<(n + 255) / 256, 256>>>();
    }
    // 2) edge scatter (4 threads per edge)
    {
        long long nthreads = (long long)N_EDGES * 4;
        int blocks = (int)((nthreads + 255) / 256);
        edge_scatter_kernel<<<blocks, 256>>>(xe4, W4, src, dst);
    }
    // 3) per-node mix (one warp per node)
    {
        long long nthreads = (long long)N_NODES * 32;
        int blocks = (int)((nthreads + 255) / 256);
        node_mix_kernel<<<blocks, 256>>>(M1, M2, out);
    }
}